// round 1
// baseline (speedup 1.0000x reference)
#include <cuda_runtime.h>
#include <math.h>

// Problem constants
// B=4, N=1024, D=1024, H=16, DH=64, layers=3
#define MROWS 4096          // B*N
#define DIM   1024
#define NSEQ  1024
#define NHEAD 16
#define DH    64
#define NLAYER 3

// ---------------- scratch (device globals; no allocation allowed) ----------
__device__ float g_xn[(size_t)MROWS * DIM];            // RMSNorm output
__device__ float g_pa[(size_t)MROWS * DIM];            // ping
__device__ float g_pb[(size_t)MROWS * DIM];            // pong
__device__ float g_k[NLAYER][(size_t)MROWS * DIM];     // K projections
__device__ float g_v[NLAYER][(size_t)MROWS * DIM];     // V projections
__device__ float g_cos[NSEQ * (DH / 2)];               // RoPE tables (fp64-accurate)
__device__ float g_sin[NSEQ * (DH / 2)];

// ---------------- RoPE tables (double precision, matches reference fp64) ----
__global__ void rope_tables_kernel() {
    int idx = blockIdx.x * blockDim.x + threadIdx.x;
    if (idx >= NSEQ * (DH / 2)) return;
    int pos = idx >> 5;          // / 32
    int p   = idx & 31;
    double inv = pow(10000.0, -((double)(2 * p)) / (double)DH);
    double a = (double)pos * inv;
    g_cos[idx] = (float)cos(a);
    g_sin[idx] = (float)sin(a);
}

// ---------------- RMSNorm: one block per row ------------------------------
__global__ __launch_bounds__(256) void rmsnorm_kernel(
    const float* __restrict__ T, const float* __restrict__ gamma,
    float* __restrict__ X)
{
    int row = blockIdx.x;
    int tid = threadIdx.x;
    const float4* t4 = (const float4*)(T + (size_t)row * DIM);
    float4 v = t4[tid];
    float s = v.x * v.x + v.y * v.y + v.z * v.z + v.w * v.w;
    #pragma unroll
    for (int o = 16; o > 0; o >>= 1) s += __shfl_xor_sync(0xffffffffu, s, o);
    __shared__ float ws[8];
    if ((tid & 31) == 0) ws[tid >> 5] = s;
    __syncthreads();
    float tot = 0.f;
    #pragma unroll
    for (int i = 0; i < 8; i++) tot += ws[i];
    float rs = rsqrtf(tot * (1.0f / (float)DIM) + 1.1920929e-07f);
    float4 g = ((const float4*)gamma)[tid];
    float4 o = make_float4(v.x * rs * g.x, v.y * rs * g.y,
                           v.z * rs * g.z, v.w * rs * g.w);
    ((float4*)(X + (size_t)row * DIM))[tid] = o;
}

// ---------------- SGEMM: C[M,1024] = A[M,1024] * B[1024,1024] --------------
// 128x128 block tile, 16 k-tile, 8x8 per-thread microtile, 256 threads.
__global__ __launch_bounds__(256) void sgemm_kernel(
    const float* __restrict__ A, const float* __restrict__ B,
    float* __restrict__ C)
{
    const int K = DIM, N = DIM;
    __shared__ float As[16][132];   // transposed A tile, padded
    __shared__ float Bs[16][132];
    int tid = threadIdx.x;
    int tx = tid & 15, ty = tid >> 4;
    const float* Ab = A + (size_t)blockIdx.y * 128 * K;
    const float* Bb = B + blockIdx.x * 128;

    float acc[8][8];
    #pragma unroll
    for (int i = 0; i < 8; i++)
        #pragma unroll
        for (int j = 0; j < 8; j++) acc[i][j] = 0.f;

    for (int k0 = 0; k0 < K; k0 += 16) {
        #pragma unroll
        for (int l = 0; l < 2; l++) {
            int f = tid + l * 256;
            int m = f >> 2, kk = (f & 3) * 4;
            float4 av = *(const float4*)(Ab + (size_t)m * K + k0 + kk);
            As[kk + 0][m] = av.x; As[kk + 1][m] = av.y;
            As[kk + 2][m] = av.z; As[kk + 3][m] = av.w;
            int kr = f >> 5, n4 = (f & 31) * 4;
            float4 bv = *(const float4*)(Bb + (size_t)(k0 + kr) * N + n4);
            *(float4*)&Bs[kr][n4] = bv;
        }
        __syncthreads();
        #pragma unroll
        for (int k = 0; k < 16; k++) {
            float a[8], b[8];
            *(float4*)&a[0] = *(const float4*)&As[k][ty * 8];
            *(float4*)&a[4] = *(const float4*)&As[k][ty * 8 + 4];
            *(float4*)&b[0] = *(const float4*)&Bs[k][tx * 8];
            *(float4*)&b[4] = *(const float4*)&Bs[k][tx * 8 + 4];
            #pragma unroll
            for (int i = 0; i < 8; i++)
                #pragma unroll
                for (int j = 0; j < 8; j++)
                    acc[i][j] = fmaf(a[i], b[j], acc[i][j]);
        }
        __syncthreads();
    }
    float* Cb = C + ((size_t)blockIdx.y * 128 + ty * 8) * N + blockIdx.x * 128 + tx * 8;
    #pragma unroll
    for (int i = 0; i < 8; i++) {
        *(float4*)&Cb[(size_t)i * N]     = make_float4(acc[i][0], acc[i][1], acc[i][2], acc[i][3]);
        *(float4*)&Cb[(size_t)i * N + 4] = make_float4(acc[i][4], acc[i][5], acc[i][6], acc[i][7]);
    }
}

// ---------------- Fused causal flash attention with RoPE -------------------
// grid: (qb=16, h=16, b=4); block: 256 threads (16x16), 64-query tile.
// Layout of Q/K/V/O in gmem: [b, n, h*64 + d]  (== merged-heads row-major).
#define SST 65   // smem row stride (padding kills the 16-way conflicts)

__global__ __launch_bounds__(256) void attn_kernel(
    const float* __restrict__ Qg, const float* __restrict__ Kg,
    const float* __restrict__ Vg, float* __restrict__ Og, int do_silu)
{
    extern __shared__ float smbuf[];
    float* Qs = smbuf;                 // 64 x SST
    float* Ks = Qs + 64 * SST;
    float* Vs = Ks + 64 * SST;
    float* Ps = Vs + 64 * SST;

    int qb = blockIdx.x, h = blockIdx.y, b = blockIdx.z;
    int tid = threadIdx.x;
    int tx = tid & 15, ty = tid >> 4;
    int q0 = qb * 64;
    size_t base = ((size_t)b * NSEQ) * DIM + h * DH;

    // load Q tile, apply RoPE
    #pragma unroll
    for (int l = 0; l < 8; l++) {
        int e = tid + l * 256;          // pair index in 64x32
        int m = e >> 5, p = e & 31;
        int pos = q0 + m;
        const float* src = Qg + base + (size_t)pos * DIM + 2 * p;
        float x0 = src[0], x1 = src[1];
        float c = g_cos[pos * 32 + p], s = g_sin[pos * 32 + p];
        Qs[m * SST + 2 * p]     = x0 * c - x1 * s;
        Qs[m * SST + 2 * p + 1] = x1 * c + x0 * s;
    }

    float mi[4], li[4], acc[4][4];
    #pragma unroll
    for (int i = 0; i < 4; i++) {
        mi[i] = -INFINITY; li[i] = 0.f;
        #pragma unroll
        for (int j = 0; j < 4; j++) acc[i][j] = 0.f;
    }
    __syncthreads();

    for (int kb = 0; kb <= qb; kb++) {
        int k0 = kb * 64;
        // load K (RoPE) + V tiles
        #pragma unroll
        for (int l = 0; l < 8; l++) {
            int e = tid + l * 256;
            int m = e >> 5, p = e & 31;
            int pos = k0 + m;
            const float* ksrc = Kg + base + (size_t)pos * DIM + 2 * p;
            float x0 = ksrc[0], x1 = ksrc[1];
            float c = g_cos[pos * 32 + p], s = g_sin[pos * 32 + p];
            Ks[m * SST + 2 * p]     = x0 * c - x1 * s;
            Ks[m * SST + 2 * p + 1] = x1 * c + x0 * s;
            const float* vsrc = Vg + base + (size_t)pos * DIM + 2 * p;
            Vs[m * SST + 2 * p]     = vsrc[0];
            Vs[m * SST + 2 * p + 1] = vsrc[1];
        }
        __syncthreads();

        // S = Q K^T for 4x4 microtile
        float S[4][4];
        #pragma unroll
        for (int i = 0; i < 4; i++)
            #pragma unroll
            for (int j = 0; j < 4; j++) S[i][j] = 0.f;
        #pragma unroll 8
        for (int d = 0; d < DH; d++) {
            float a[4], bb[4];
            #pragma unroll
            for (int i = 0; i < 4; i++) a[i] = Qs[(ty * 4 + i) * SST + d];
            #pragma unroll
            for (int j = 0; j < 4; j++) bb[j] = Ks[(tx * 4 + j) * SST + d];
            #pragma unroll
            for (int i = 0; i < 4; i++)
                #pragma unroll
                for (int j = 0; j < 4; j++)
                    S[i][j] = fmaf(a[i], bb[j], S[i][j]);
        }

        bool isdiag = (kb == qb);
        #pragma unroll
        for (int i = 0; i < 4; i++) {
            int qr = q0 + ty * 4 + i;
            #pragma unroll
            for (int j = 0; j < 4; j++) {
                int kc = k0 + tx * 4 + j;
                S[i][j] = (!isdiag || kc <= qr) ? S[i][j] * 0.125f : -INFINITY;
            }
            float rm = fmaxf(fmaxf(S[i][0], S[i][1]), fmaxf(S[i][2], S[i][3]));
            #pragma unroll
            for (int o = 8; o > 0; o >>= 1)
                rm = fmaxf(rm, __shfl_xor_sync(0xffffffffu, rm, o));
            float mn = fmaxf(mi[i], rm);
            float corr = __expf(mi[i] - mn);
            mi[i] = mn;
            float rs = 0.f;
            #pragma unroll
            for (int j = 0; j < 4; j++) {
                float e = __expf(S[i][j] - mn);
                S[i][j] = e; rs += e;
            }
            #pragma unroll
            for (int o = 8; o > 0; o >>= 1)
                rs += __shfl_xor_sync(0xffffffffu, rs, o);
            li[i] = li[i] * corr + rs;
            #pragma unroll
            for (int j = 0; j < 4; j++) acc[i][j] *= corr;
            #pragma unroll
            for (int j = 0; j < 4; j++)
                Ps[(ty * 4 + i) * SST + tx * 4 + j] = S[i][j];
        }
        __syncthreads();

        // O += P @ V  (output cols owned by tx)
        #pragma unroll 8
        for (int k = 0; k < 64; k++) {
            float pv[4], vv[4];
            #pragma unroll
            for (int i = 0; i < 4; i++) pv[i] = Ps[(ty * 4 + i) * SST + k];
            #pragma unroll
            for (int j = 0; j < 4; j++) vv[j] = Vs[k * SST + tx * 4 + j];
            #pragma unroll
            for (int i = 0; i < 4; i++)
                #pragma unroll
                for (int j = 0; j < 4; j++)
                    acc[i][j] = fmaf(pv[i], vv[j], acc[i][j]);
        }
        __syncthreads();
    }

    // normalize, optional SiLU, store
    #pragma unroll
    for (int i = 0; i < 4; i++) {
        float inv = 1.0f / li[i];
        int qr = q0 + ty * 4 + i;
        float* dst = Og + base + (size_t)qr * DIM + tx * 4;
        float v0[4];
        #pragma unroll
        for (int j = 0; j < 4; j++) {
            float v = acc[i][j] * inv;
            if (do_silu) v = v / (1.0f + __expf(-v));
            v0[j] = v;
        }
        *(float4*)dst = make_float4(v0[0], v0[1], v0[2], v0[3]);
    }
}

// ---------------- launch ----------------------------------------------------
extern "C" void kernel_launch(void* const* d_in, const int* in_sizes, int n_in,
                              void* d_out, int out_size)
{
    const float* tokens = (const float*)d_in[0];
    const float* gamma  = (const float*)d_in[1];
    const float* Wq     = (const float*)d_in[2];
    const float* Wk     = (const float*)d_in[3];
    const float* Wv     = (const float*)d_in[4];
    const float* Wo     = (const float*)d_in[5];
    float* out = (float*)d_out;

    float *xn, *pa, *pb, *kb, *vb;
    cudaGetSymbolAddress((void**)&xn, g_xn);
    cudaGetSymbolAddress((void**)&pa, g_pa);
    cudaGetSymbolAddress((void**)&pb, g_pb);
    cudaGetSymbolAddress((void**)&kb, g_k);
    cudaGetSymbolAddress((void**)&vb, g_v);

    const size_t SZ  = (size_t)MROWS * DIM;   // per-layer K/V scratch stride
    const size_t SZW = (size_t)DIM * DIM;     // per-layer weight stride

    rope_tables_kernel<<<(NSEQ * 32 + 255) / 256, 256>>>();
    rmsnorm_kernel<<<MROWS, 256>>>(tokens, gamma, xn);

    dim3 gg(DIM / 128, MROWS / 128);          // (8, 32)
    sgemm_kernel<<<gg, 256>>>(xn, Wq, pa);
    for (int i = 0; i < NLAYER; i++) {
        sgemm_kernel<<<gg, 256>>>(xn, Wk + SZW * i, kb + SZ * i);
        sgemm_kernel<<<gg, 256>>>(xn, Wv + SZW * i, vb + SZ * i);
    }

    size_t smem = (size_t)4 * 64 * SST * sizeof(float);   // 66,560 B
    cudaFuncSetAttribute(attn_kernel,
                         cudaFuncAttributeMaxDynamicSharedMemorySize, (int)smem);
    dim3 ga(NSEQ / 64, NHEAD, 4);             // (16, 16, 4)
    attn_kernel<<<ga, 256, smem>>>(pa, kb,          vb,          pb, 1);
    attn_kernel<<<ga, 256, smem>>>(pb, kb + SZ,     vb + SZ,     pa, 1);
    attn_kernel<<<ga, 256, smem>>>(pa, kb + 2 * SZ, vb + 2 * SZ, pb, 0);

    sgemm_kernel<<<gg, 256>>>(pb, Wo, out);
}

// round 2
// speedup vs baseline: 1.4115x; 1.4115x over previous
#include <cuda_runtime.h>
#include <math.h>
#include <stdint.h>

// Problem constants: B=4, N=1024, D=1024, H=16, DH=64, layers=3
#define MROWS 4096
#define DIM   1024
#define NSEQ  1024
#define NHEAD 16
#define DH    64
#define NLAYER 3

// ---------------- scratch (device globals; no allocation allowed) ----------
__device__ float g_xn[(size_t)MROWS * DIM];
__device__ float g_pa[(size_t)MROWS * DIM];
__device__ float g_pb[(size_t)MROWS * DIM];
__device__ float g_k[NLAYER][(size_t)MROWS * DIM];
__device__ float g_v[NLAYER][(size_t)MROWS * DIM];
__device__ float g_cos[NSEQ * (DH / 2)];
__device__ float g_sin[NSEQ * (DH / 2)];

// ---------------- RoPE tables (fp64, matches reference) --------------------
__global__ void rope_tables_kernel() {
    int idx = blockIdx.x * blockDim.x + threadIdx.x;
    if (idx >= NSEQ * (DH / 2)) return;
    int pos = idx >> 5;
    int p   = idx & 31;
    double inv = pow(10000.0, -((double)(2 * p)) / (double)DH);
    double a = (double)pos * inv;
    g_cos[idx] = (float)cos(a);
    g_sin[idx] = (float)sin(a);
}

// ---------------- RMSNorm ---------------------------------------------------
__global__ __launch_bounds__(256) void rmsnorm_kernel(
    const float* __restrict__ T, const float* __restrict__ gamma,
    float* __restrict__ X)
{
    int row = blockIdx.x;
    int tid = threadIdx.x;
    const float4* t4 = (const float4*)(T + (size_t)row * DIM);
    float4 v = t4[tid];
    float s = v.x * v.x + v.y * v.y + v.z * v.z + v.w * v.w;
    #pragma unroll
    for (int o = 16; o > 0; o >>= 1) s += __shfl_xor_sync(0xffffffffu, s, o);
    __shared__ float ws[8];
    if ((tid & 31) == 0) ws[tid >> 5] = s;
    __syncthreads();
    float tot = 0.f;
    #pragma unroll
    for (int i = 0; i < 8; i++) tot += ws[i];
    float rs = rsqrtf(tot * (1.0f / (float)DIM) + 1.1920929e-07f);
    float4 g = ((const float4*)gamma)[tid];
    ((float4*)(X + (size_t)row * DIM))[tid] =
        make_float4(v.x * rs * g.x, v.y * rs * g.y, v.z * rs * g.z, v.w * rs * g.w);
}

// ---------------- TF32 tensor-core GEMM ------------------------------------
// C[M,1024] = A[M,1024] * B[1024,1024], 128x128 tile, BK=32, 256 threads.
// Warp grid 2(m) x 4(n); warp tile 64x32; mma.m16n8k8 tf32, fp32 accum.
#define AST 36     // A smem row stride (words): bank = 4g+tg, conflict-free
#define BST 136    // B smem row stride (words): bank = 8tg+g, conflict-free
#define ASZ (128 * AST)
#define BSZ (32 * BST)

__device__ __forceinline__ uint32_t f2tf(float x) {
    uint32_t r;
    asm("cvt.rna.tf32.f32 %0, %1;" : "=r"(r) : "f"(x));
    return r;
}

__device__ __forceinline__ void mma_tf32(
    float c[4], const uint32_t a[4], const uint32_t b[2])
{
    asm volatile(
        "mma.sync.aligned.m16n8k8.row.col.f32.tf32.tf32.f32 "
        "{%0,%1,%2,%3}, {%4,%5,%6,%7}, {%8,%9}, {%0,%1,%2,%3};\n"
        : "+f"(c[0]), "+f"(c[1]), "+f"(c[2]), "+f"(c[3])
        : "r"(a[0]), "r"(a[1]), "r"(a[2]), "r"(a[3]), "r"(b[0]), "r"(b[1]));
}

__global__ __launch_bounds__(256) void tgemm_kernel(
    const float* __restrict__ A, const float* __restrict__ B,
    float* __restrict__ C)
{
    const int K = DIM, Nn = DIM;
    extern __shared__ uint32_t sm[];
    uint32_t* As0 = sm;
    uint32_t* As1 = sm + ASZ;
    uint32_t* Bs0 = sm + 2 * ASZ;
    uint32_t* Bs1 = sm + 2 * ASZ + BSZ;

    int tid = threadIdx.x;
    int wid = tid >> 5, lane = tid & 31;
    int g = lane >> 2, tg = lane & 3;          // mma group / thread-in-group
    int warp_m = (wid & 1) * 64;
    int warp_n = (wid >> 1) * 32;

    const float* Ab = A + (size_t)blockIdx.y * 128 * K;
    const float* Bb = B + blockIdx.x * 128;

    // gmem staging coords
    int am = tid >> 1;                 // A row 0..127 (2 threads/row)
    int ak4 = (tid & 1) * 16;          // this thread covers k4 = ak4, ak4+4, ak4+8, ak4+12
    int bk = tid >> 3;                 // B k-row 0..31
    int bn4 = (tid & 7) * 16;          // n start; covers 4 float4

    float acc[4][4][4];
    #pragma unroll
    for (int mt = 0; mt < 4; mt++)
        #pragma unroll
        for (int nt = 0; nt < 4; nt++)
            #pragma unroll
            for (int r = 0; r < 4; r++) acc[mt][nt][r] = 0.f;

    float4 areg[4], breg[4];

    // preload tile 0
    #pragma unroll
    for (int i = 0; i < 4; i++) {
        areg[i] = *(const float4*)(Ab + (size_t)am * K + ak4 + 4 * i);
        breg[i] = *(const float4*)(Bb + (size_t)(bk) * Nn + bn4 + 4 * i);
    }
    #pragma unroll
    for (int i = 0; i < 4; i++) {
        *(uint4*)&As0[am * AST + ak4 + 4 * i] =
            make_uint4(f2tf(areg[i].x), f2tf(areg[i].y), f2tf(areg[i].z), f2tf(areg[i].w));
        *(uint4*)&Bs0[bk * BST + bn4 + 4 * i] =
            make_uint4(f2tf(breg[i].x), f2tf(breg[i].y), f2tf(breg[i].z), f2tf(breg[i].w));
    }
    __syncthreads();

    uint32_t *Asr = As0, *Asw = As1, *Bsr = Bs0, *Bsw = Bs1;

    for (int kt = 0; kt < K / 32; kt++) {
        int k0n = (kt + 1) * 32;
        if (kt < K / 32 - 1) {
            #pragma unroll
            for (int i = 0; i < 4; i++) {
                areg[i] = *(const float4*)(Ab + (size_t)am * K + k0n + ak4 + 4 * i);
                breg[i] = *(const float4*)(Bb + (size_t)(k0n + bk) * Nn + bn4 + 4 * i);
            }
        }

        // compute on current buffers
        #pragma unroll
        for (int ks = 0; ks < 4; ks++) {
            int kk = ks * 8;
            uint32_t afr[4][4], bfr[4][2];
            #pragma unroll
            for (int mt = 0; mt < 4; mt++) {
                int r0 = warp_m + mt * 16 + g;
                afr[mt][0] = Asr[r0 * AST + kk + tg];
                afr[mt][1] = Asr[(r0 + 8) * AST + kk + tg];
                afr[mt][2] = Asr[r0 * AST + kk + tg + 4];
                afr[mt][3] = Asr[(r0 + 8) * AST + kk + tg + 4];
            }
            #pragma unroll
            for (int nt = 0; nt < 4; nt++) {
                int nc = warp_n + nt * 8 + g;
                bfr[nt][0] = Bsr[(kk + tg) * BST + nc];
                bfr[nt][1] = Bsr[(kk + tg + 4) * BST + nc];
            }
            #pragma unroll
            for (int mt = 0; mt < 4; mt++)
                #pragma unroll
                for (int nt = 0; nt < 4; nt++)
                    mma_tf32(acc[mt][nt], afr[mt], bfr[nt]);
        }

        if (kt < K / 32 - 1) {
            #pragma unroll
            for (int i = 0; i < 4; i++) {
                *(uint4*)&Asw[am * AST + ak4 + 4 * i] =
                    make_uint4(f2tf(areg[i].x), f2tf(areg[i].y), f2tf(areg[i].z), f2tf(areg[i].w));
                *(uint4*)&Bsw[bk * BST + bn4 + 4 * i] =
                    make_uint4(f2tf(breg[i].x), f2tf(breg[i].y), f2tf(breg[i].z), f2tf(breg[i].w));
            }
            uint32_t* t;
            t = Asr; Asr = Asw; Asw = t;
            t = Bsr; Bsr = Bsw; Bsw = t;
        }
        __syncthreads();
    }

    // epilogue: c0,c1 at (row, 2tg), (row, 2tg+1); c2,c3 at row+8
    float* Cb = C + ((size_t)blockIdx.y * 128 + warp_m + g) * Nn
                  + blockIdx.x * 128 + warp_n + 2 * tg;
    #pragma unroll
    for (int mt = 0; mt < 4; mt++) {
        #pragma unroll
        for (int nt = 0; nt < 4; nt++) {
            float* p = Cb + (size_t)(mt * 16) * Nn + nt * 8;
            *(float2*)p = make_float2(acc[mt][nt][0], acc[mt][nt][1]);
            *(float2*)(p + (size_t)8 * Nn) = make_float2(acc[mt][nt][2], acc[mt][nt][3]);
        }
    }
}

// ---------------- Fused causal flash attention with RoPE -------------------
#define SST 65

__global__ __launch_bounds__(256) void attn_kernel(
    const float* __restrict__ Qg, const float* __restrict__ Kg,
    const float* __restrict__ Vg, float* __restrict__ Og, int do_silu)
{
    extern __shared__ float smbuf[];
    float* Qs = smbuf;
    float* Ks = Qs + 64 * SST;
    float* Vs = Ks + 64 * SST;
    float* Ps = Vs + 64 * SST;

    int qb = blockIdx.x, h = blockIdx.y, b = blockIdx.z;
    int tid = threadIdx.x;
    int tx = tid & 15, ty = tid >> 4;
    int q0 = qb * 64;
    size_t base = ((size_t)b * NSEQ) * DIM + h * DH;

    #pragma unroll
    for (int l = 0; l < 8; l++) {
        int e = tid + l * 256;
        int m = e >> 5, p = e & 31;
        int pos = q0 + m;
        const float* src = Qg + base + (size_t)pos * DIM + 2 * p;
        float x0 = src[0], x1 = src[1];
        float c = g_cos[pos * 32 + p], s = g_sin[pos * 32 + p];
        Qs[m * SST + 2 * p]     = x0 * c - x1 * s;
        Qs[m * SST + 2 * p + 1] = x1 * c + x0 * s;
    }

    float mi[4], li[4], acc[4][4];
    #pragma unroll
    for (int i = 0; i < 4; i++) {
        mi[i] = -INFINITY; li[i] = 0.f;
        #pragma unroll
        for (int j = 0; j < 4; j++) acc[i][j] = 0.f;
    }
    __syncthreads();

    for (int kb = 0; kb <= qb; kb++) {
        int k0 = kb * 64;
        #pragma unroll
        for (int l = 0; l < 8; l++) {
            int e = tid + l * 256;
            int m = e >> 5, p = e & 31;
            int pos = k0 + m;
            const float* ksrc = Kg + base + (size_t)pos * DIM + 2 * p;
            float x0 = ksrc[0], x1 = ksrc[1];
            float c = g_cos[pos * 32 + p], s = g_sin[pos * 32 + p];
            Ks[m * SST + 2 * p]     = x0 * c - x1 * s;
            Ks[m * SST + 2 * p + 1] = x1 * c + x0 * s;
            const float* vsrc = Vg + base + (size_t)pos * DIM + 2 * p;
            Vs[m * SST + 2 * p]     = vsrc[0];
            Vs[m * SST + 2 * p + 1] = vsrc[1];
        }
        __syncthreads();

        float S[4][4];
        #pragma unroll
        for (int i = 0; i < 4; i++)
            #pragma unroll
            for (int j = 0; j < 4; j++) S[i][j] = 0.f;
        #pragma unroll 8
        for (int d = 0; d < DH; d++) {
            float a[4], bb[4];
            #pragma unroll
            for (int i = 0; i < 4; i++) a[i] = Qs[(ty * 4 + i) * SST + d];
            #pragma unroll
            for (int j = 0; j < 4; j++) bb[j] = Ks[(tx * 4 + j) * SST + d];
            #pragma unroll
            for (int i = 0; i < 4; i++)
                #pragma unroll
                for (int j = 0; j < 4; j++)
                    S[i][j] = fmaf(a[i], bb[j], S[i][j]);
        }

        bool isdiag = (kb == qb);
        #pragma unroll
        for (int i = 0; i < 4; i++) {
            int qr = q0 + ty * 4 + i;
            #pragma unroll
            for (int j = 0; j < 4; j++) {
                int kc = k0 + tx * 4 + j;
                S[i][j] = (!isdiag || kc <= qr) ? S[i][j] * 0.125f : -INFINITY;
            }
            float rm = fmaxf(fmaxf(S[i][0], S[i][1]), fmaxf(S[i][2], S[i][3]));
            #pragma unroll
            for (int o = 8; o > 0; o >>= 1)
                rm = fmaxf(rm, __shfl_xor_sync(0xffffffffu, rm, o));
            float mn = fmaxf(mi[i], rm);
            float corr = __expf(mi[i] - mn);
            mi[i] = mn;
            float rs = 0.f;
            #pragma unroll
            for (int j = 0; j < 4; j++) {
                float e = __expf(S[i][j] - mn);
                S[i][j] = e; rs += e;
            }
            #pragma unroll
            for (int o = 8; o > 0; o >>= 1)
                rs += __shfl_xor_sync(0xffffffffu, rs, o);
            li[i] = li[i] * corr + rs;
            #pragma unroll
            for (int j = 0; j < 4; j++) acc[i][j] *= corr;
            #pragma unroll
            for (int j = 0; j < 4; j++)
                Ps[(ty * 4 + i) * SST + tx * 4 + j] = S[i][j];
        }
        __syncthreads();

        #pragma unroll 8
        for (int k = 0; k < 64; k++) {
            float pv[4], vv[4];
            #pragma unroll
            for (int i = 0; i < 4; i++) pv[i] = Ps[(ty * 4 + i) * SST + k];
            #pragma unroll
            for (int j = 0; j < 4; j++) vv[j] = Vs[k * SST + tx * 4 + j];
            #pragma unroll
            for (int i = 0; i < 4; i++)
                #pragma unroll
                for (int j = 0; j < 4; j++)
                    acc[i][j] = fmaf(pv[i], vv[j], acc[i][j]);
        }
        __syncthreads();
    }

    #pragma unroll
    for (int i = 0; i < 4; i++) {
        float inv = 1.0f / li[i];
        int qr = q0 + ty * 4 + i;
        float* dst = Og + base + (size_t)qr * DIM + tx * 4;
        float v0[4];
        #pragma unroll
        for (int j = 0; j < 4; j++) {
            float v = acc[i][j] * inv;
            if (do_silu) v = v / (1.0f + __expf(-v));
            v0[j] = v;
        }
        *(float4*)dst = make_float4(v0[0], v0[1], v0[2], v0[3]);
    }
}

// ---------------- launch ----------------------------------------------------
extern "C" void kernel_launch(void* const* d_in, const int* in_sizes, int n_in,
                              void* d_out, int out_size)
{
    const float* tokens = (const float*)d_in[0];
    const float* gamma  = (const float*)d_in[1];
    const float* Wq     = (const float*)d_in[2];
    const float* Wk     = (const float*)d_in[3];
    const float* Wv     = (const float*)d_in[4];
    const float* Wo     = (const float*)d_in[5];
    float* out = (float*)d_out;

    float *xn, *pa, *pb, *kb, *vb;
    cudaGetSymbolAddress((void**)&xn, g_xn);
    cudaGetSymbolAddress((void**)&pa, g_pa);
    cudaGetSymbolAddress((void**)&pb, g_pb);
    cudaGetSymbolAddress((void**)&kb, g_k);
    cudaGetSymbolAddress((void**)&vb, g_v);

    const size_t SZ  = (size_t)MROWS * DIM;
    const size_t SZW = (size_t)DIM * DIM;

    rope_tables_kernel<<<(NSEQ * 32 + 255) / 256, 256>>>();
    rmsnorm_kernel<<<MROWS, 256>>>(tokens, gamma, xn);

    size_t gsm = (size_t)(2 * ASZ + 2 * BSZ) * sizeof(uint32_t);  // 71,680 B
    cudaFuncSetAttribute(tgemm_kernel,
                         cudaFuncAttributeMaxDynamicSharedMemorySize, (int)gsm);

    dim3 gg(DIM / 128, MROWS / 128);
    tgemm_kernel<<<gg, 256, gsm>>>(xn, Wq, pa);
    for (int i = 0; i < NLAYER; i++) {
        tgemm_kernel<<<gg, 256, gsm>>>(xn, Wk + SZW * i, kb + SZ * i);
        tgemm_kernel<<<gg, 256, gsm>>>(xn, Wv + SZW * i, vb + SZ * i);
    }

    size_t smem = (size_t)4 * 64 * SST * sizeof(float);
    cudaFuncSetAttribute(attn_kernel,
                         cudaFuncAttributeMaxDynamicSharedMemorySize, (int)smem);
    dim3 ga(NSEQ / 64, NHEAD, 4);
    attn_kernel<<<ga, 256, smem>>>(pa, kb,          vb,          pb, 1);
    attn_kernel<<<ga, 256, smem>>>(pb, kb + SZ,     vb + SZ,     pa, 1);
    attn_kernel<<<ga, 256, smem>>>(pa, kb + 2 * SZ, vb + 2 * SZ, pb, 0);

    tgemm_kernel<<<gg, 256, gsm>>>(pb, Wo, out);
}

// round 3
// speedup vs baseline: 2.2074x; 1.5639x over previous
#include <cuda_runtime.h>
#include <math.h>
#include <stdint.h>

// Problem constants: B=4, N=1024, D=1024, H=16, DH=64, layers=3
#define MROWS 4096
#define DIM   1024
#define NSEQ  1024
#define NHEAD 16
#define DH    64
#define NLAYER 3

// ---------------- scratch (device globals; no allocation allowed) ----------
__device__ float g_xn[(size_t)MROWS * DIM];
__device__ float g_pa[(size_t)MROWS * DIM];
__device__ float g_pb[(size_t)MROWS * DIM];
__device__ float g_k[NLAYER][(size_t)MROWS * DIM];
__device__ float g_v[NLAYER][(size_t)MROWS * DIM];
__device__ float g_cos[NSEQ * (DH / 2)];
__device__ float g_sin[NSEQ * (DH / 2)];

// ---------------- RoPE tables (fp64, matches reference) --------------------
__global__ void rope_tables_kernel() {
    int idx = blockIdx.x * blockDim.x + threadIdx.x;
    if (idx >= NSEQ * (DH / 2)) return;
    int pos = idx >> 5;
    int p   = idx & 31;
    double inv = pow(10000.0, -((double)(2 * p)) / (double)DH);
    double a = (double)pos * inv;
    g_cos[idx] = (float)cos(a);
    g_sin[idx] = (float)sin(a);
}

// ---------------- RMSNorm ---------------------------------------------------
__global__ __launch_bounds__(256) void rmsnorm_kernel(
    const float* __restrict__ T, const float* __restrict__ gamma,
    float* __restrict__ X)
{
    int row = blockIdx.x;
    int tid = threadIdx.x;
    const float4* t4 = (const float4*)(T + (size_t)row * DIM);
    float4 v = t4[tid];
    float s = v.x * v.x + v.y * v.y + v.z * v.z + v.w * v.w;
    #pragma unroll
    for (int o = 16; o > 0; o >>= 1) s += __shfl_xor_sync(0xffffffffu, s, o);
    __shared__ float ws[8];
    if ((tid & 31) == 0) ws[tid >> 5] = s;
    __syncthreads();
    float tot = 0.f;
    #pragma unroll
    for (int i = 0; i < 8; i++) tot += ws[i];
    float rs = rsqrtf(tot * (1.0f / (float)DIM) + 1.1920929e-07f);
    float4 g = ((const float4*)gamma)[tid];
    ((float4*)(X + (size_t)row * DIM))[tid] =
        make_float4(v.x * rs * g.x, v.y * rs * g.y, v.z * rs * g.z, v.w * rs * g.w);
}

// ---------------- TF32 mma helpers ------------------------------------------
__device__ __forceinline__ uint32_t f2tf(float x) {
    uint32_t r;
    asm("cvt.rna.tf32.f32 %0, %1;" : "=r"(r) : "f"(x));
    return r;
}

__device__ __forceinline__ void mma_tf32(
    float c[4], const uint32_t a[4], const uint32_t b[2])
{
    asm volatile(
        "mma.sync.aligned.m16n8k8.row.col.f32.tf32.tf32.f32 "
        "{%0,%1,%2,%3}, {%4,%5,%6,%7}, {%8,%9}, {%0,%1,%2,%3};\n"
        : "+f"(c[0]), "+f"(c[1]), "+f"(c[2]), "+f"(c[3])
        : "r"(a[0]), "r"(a[1]), "r"(a[2]), "r"(a[3]), "r"(b[0]), "r"(b[1]));
}

// ---------------- TF32 tensor-core GEMM body --------------------------------
#define AST 36
#define BST 136
#define ASZ (128 * AST)
#define BSZ (32 * BST)

__device__ __forceinline__ void tgemm_body(
    const float* __restrict__ A, const float* __restrict__ B,
    float* __restrict__ C, int bx, int by)
{
    const int K = DIM, Nn = DIM;
    extern __shared__ uint32_t sm[];
    uint32_t* As0 = sm;
    uint32_t* As1 = sm + ASZ;
    uint32_t* Bs0 = sm + 2 * ASZ;
    uint32_t* Bs1 = sm + 2 * ASZ + BSZ;

    int tid = threadIdx.x;
    int wid = tid >> 5, lane = tid & 31;
    int g = lane >> 2, tg = lane & 3;
    int warp_m = (wid & 1) * 64;
    int warp_n = (wid >> 1) * 32;

    const float* Ab = A + (size_t)by * 128 * K;
    const float* Bb = B + bx * 128;

    int am = tid >> 1;
    int ak4 = (tid & 1) * 16;
    int bk = tid >> 3;
    int bn4 = (tid & 7) * 16;

    float acc[4][4][4];
    #pragma unroll
    for (int mt = 0; mt < 4; mt++)
        #pragma unroll
        for (int nt = 0; nt < 4; nt++)
            #pragma unroll
            for (int r = 0; r < 4; r++) acc[mt][nt][r] = 0.f;

    float4 areg[4], breg[4];
    #pragma unroll
    for (int i = 0; i < 4; i++) {
        areg[i] = *(const float4*)(Ab + (size_t)am * K + ak4 + 4 * i);
        breg[i] = *(const float4*)(Bb + (size_t)(bk) * Nn + bn4 + 4 * i);
    }
    #pragma unroll
    for (int i = 0; i < 4; i++) {
        *(uint4*)&As0[am * AST + ak4 + 4 * i] =
            make_uint4(f2tf(areg[i].x), f2tf(areg[i].y), f2tf(areg[i].z), f2tf(areg[i].w));
        *(uint4*)&Bs0[bk * BST + bn4 + 4 * i] =
            make_uint4(f2tf(breg[i].x), f2tf(breg[i].y), f2tf(breg[i].z), f2tf(breg[i].w));
    }
    __syncthreads();

    uint32_t *Asr = As0, *Asw = As1, *Bsr = Bs0, *Bsw = Bs1;

    for (int kt = 0; kt < K / 32; kt++) {
        int k0n = (kt + 1) * 32;
        if (kt < K / 32 - 1) {
            #pragma unroll
            for (int i = 0; i < 4; i++) {
                areg[i] = *(const float4*)(Ab + (size_t)am * K + k0n + ak4 + 4 * i);
                breg[i] = *(const float4*)(Bb + (size_t)(k0n + bk) * Nn + bn4 + 4 * i);
            }
        }
        #pragma unroll
        for (int ks = 0; ks < 4; ks++) {
            int kk = ks * 8;
            uint32_t afr[4][4], bfr[4][2];
            #pragma unroll
            for (int mt = 0; mt < 4; mt++) {
                int r0 = warp_m + mt * 16 + g;
                afr[mt][0] = Asr[r0 * AST + kk + tg];
                afr[mt][1] = Asr[(r0 + 8) * AST + kk + tg];
                afr[mt][2] = Asr[r0 * AST + kk + tg + 4];
                afr[mt][3] = Asr[(r0 + 8) * AST + kk + tg + 4];
            }
            #pragma unroll
            for (int nt = 0; nt < 4; nt++) {
                int nc = warp_n + nt * 8 + g;
                bfr[nt][0] = Bsr[(kk + tg) * BST + nc];
                bfr[nt][1] = Bsr[(kk + tg + 4) * BST + nc];
            }
            #pragma unroll
            for (int mt = 0; mt < 4; mt++)
                #pragma unroll
                for (int nt = 0; nt < 4; nt++)
                    mma_tf32(acc[mt][nt], afr[mt], bfr[nt]);
        }
        if (kt < K / 32 - 1) {
            #pragma unroll
            for (int i = 0; i < 4; i++) {
                *(uint4*)&Asw[am * AST + ak4 + 4 * i] =
                    make_uint4(f2tf(areg[i].x), f2tf(areg[i].y), f2tf(areg[i].z), f2tf(areg[i].w));
                *(uint4*)&Bsw[bk * BST + bn4 + 4 * i] =
                    make_uint4(f2tf(breg[i].x), f2tf(breg[i].y), f2tf(breg[i].z), f2tf(breg[i].w));
            }
            uint32_t* t;
            t = Asr; Asr = Asw; Asw = t;
            t = Bsr; Bsr = Bsw; Bsw = t;
        }
        __syncthreads();
    }

    float* Cb = C + ((size_t)by * 128 + warp_m + g) * Nn
                  + bx * 128 + warp_n + 2 * tg;
    #pragma unroll
    for (int mt = 0; mt < 4; mt++) {
        #pragma unroll
        for (int nt = 0; nt < 4; nt++) {
            float* p = Cb + (size_t)(mt * 16) * Nn + nt * 8;
            *(float2*)p = make_float2(acc[mt][nt][0], acc[mt][nt][1]);
            *(float2*)(p + (size_t)8 * Nn) = make_float2(acc[mt][nt][2], acc[mt][nt][3]);
        }
    }
}

__global__ __launch_bounds__(256) void tgemm_kernel(
    const float* __restrict__ A, const float* __restrict__ B,
    float* __restrict__ C)
{
    tgemm_body(A, B, C, blockIdx.x, blockIdx.y);
}

// Batched: z=0 -> Wq; z=1..3 -> Wk[z-1]; z=4..6 -> Wv[z-4]
__global__ __launch_bounds__(256) void tgemm7_kernel(
    const float* __restrict__ A,
    const float* __restrict__ Wq, const float* __restrict__ Wk,
    const float* __restrict__ Wv,
    float* __restrict__ Cq, float* __restrict__ Ck, float* __restrict__ Cv)
{
    const size_t SZ  = (size_t)MROWS * DIM;
    const size_t SZW = (size_t)DIM * DIM;
    int z = blockIdx.z;
    const float* B;
    float* C;
    if (z == 0)      { B = Wq;                  C = Cq; }
    else if (z < 4)  { B = Wk + SZW * (z - 1);  C = Ck + SZ * (z - 1); }
    else             { B = Wv + SZW * (z - 4);  C = Cv + SZ * (z - 4); }
    tgemm_body(A, B, C, blockIdx.x, blockIdx.y);
}

// ---------------- Tensor-core causal flash attention with RoPE --------------
// grid (16,16,4), 128 threads (4 warps). Warp w owns query rows [16w,16w+16).
// smem (tf32 words, stride 68): buf0 = Q then P (aliased), buf1 = K, buf2 = V.
#define SQT 68

__global__ __launch_bounds__(128) void attn_mma_kernel(
    const float* __restrict__ Qg, const float* __restrict__ Kg,
    const float* __restrict__ Vg, float* __restrict__ Og, int do_silu)
{
    extern __shared__ uint32_t smu[];
    uint32_t* QPs = smu;                 // 64 x SQT : Q, later P
    uint32_t* Ks  = smu + 64 * SQT;
    uint32_t* Vs  = smu + 2 * 64 * SQT;

    int qb = blockIdx.x, h = blockIdx.y, b = blockIdx.z;
    int tid = threadIdx.x;
    int wid = tid >> 5, lane = tid & 31;
    int g = lane >> 2, tg = lane & 3;
    int qrow = wid * 16;
    int q0 = qb * 64;
    size_t base = ((size_t)b * NSEQ) * DIM + h * DH;

    // ---- load Q tile: RoPE + fold scale 0.125, store tf32 ----
    #pragma unroll
    for (int l = 0; l < 16; l++) {
        int e = tid + l * 128;           // pair index in 64x32
        int m = e >> 5, p = e & 31;
        int pos = q0 + m;
        const float2 q2 = *(const float2*)(Qg + base + (size_t)pos * DIM + 2 * p);
        float c = g_cos[pos * 32 + p], s = g_sin[pos * 32 + p];
        QPs[m * SQT + 2 * p]     = f2tf((q2.x * c - q2.y * s) * 0.125f);
        QPs[m * SQT + 2 * p + 1] = f2tf((q2.y * c + q2.x * s) * 0.125f);
    }
    __syncthreads();

    // ---- preload Q fragments (8 k-tiles of 8) ----
    uint32_t qa[8][4];
    #pragma unroll
    for (int kt = 0; kt < 8; kt++) {
        qa[kt][0] = QPs[(qrow + g)     * SQT + kt * 8 + tg];
        qa[kt][1] = QPs[(qrow + g + 8) * SQT + kt * 8 + tg];
        qa[kt][2] = QPs[(qrow + g)     * SQT + kt * 8 + tg + 4];
        qa[kt][3] = QPs[(qrow + g + 8) * SQT + kt * 8 + tg + 4];
    }

    float m0 = -INFINITY, m1 = -INFINITY, l0 = 0.f, l1 = 0.f;
    float oacc[8][4];
    #pragma unroll
    for (int nt = 0; nt < 8; nt++)
        #pragma unroll
        for (int r = 0; r < 4; r++) oacc[nt][r] = 0.f;

    int aq0 = q0 + qrow + g;
    int aq1 = aq0 + 8;

    for (int kb = 0; kb <= qb; kb++) {
        int k0 = kb * 64;
        // ---- load K (RoPE) + V, store tf32 ----
        #pragma unroll
        for (int l = 0; l < 16; l++) {
            int e = tid + l * 128;
            int m = e >> 5, p = e & 31;
            int pos = k0 + m;
            const float2 k2 = *(const float2*)(Kg + base + (size_t)pos * DIM + 2 * p);
            float c = g_cos[pos * 32 + p], s = g_sin[pos * 32 + p];
            Ks[m * SQT + 2 * p]     = f2tf(k2.x * c - k2.y * s);
            Ks[m * SQT + 2 * p + 1] = f2tf(k2.y * c + k2.x * s);
            const float2 v2 = *(const float2*)(Vg + base + (size_t)pos * DIM + 2 * p);
            Vs[m * SQT + 2 * p]     = f2tf(v2.x);
            Vs[m * SQT + 2 * p + 1] = f2tf(v2.y);
        }
        __syncthreads();

        // ---- S = Q K^T : 8 n-tiles x 8 k-tiles of mma ----
        float S[8][4];
        #pragma unroll
        for (int nt = 0; nt < 8; nt++)
            #pragma unroll
            for (int r = 0; r < 4; r++) S[nt][r] = 0.f;
        #pragma unroll
        for (int kt = 0; kt < 8; kt++) {
            uint32_t bfr[8][2];
            #pragma unroll
            for (int nt = 0; nt < 8; nt++) {
                bfr[nt][0] = Ks[(nt * 8 + g) * SQT + kt * 8 + tg];
                bfr[nt][1] = Ks[(nt * 8 + g) * SQT + kt * 8 + tg + 4];
            }
            #pragma unroll
            for (int nt = 0; nt < 8; nt++)
                mma_tf32(S[nt], qa[kt], bfr[nt]);
        }

        // ---- causal mask on diagonal block ----
        if (kb == qb) {
            #pragma unroll
            for (int nt = 0; nt < 8; nt++) {
                int c0 = k0 + nt * 8 + 2 * tg;
                if (c0 > aq0)     S[nt][0] = -INFINITY;
                if (c0 + 1 > aq0) S[nt][1] = -INFINITY;
                if (c0 > aq1)     S[nt][2] = -INFINITY;
                if (c0 + 1 > aq1) S[nt][3] = -INFINITY;
            }
        }

        // ---- online softmax (rows g and g+8) ----
        float rm0 = -INFINITY, rm1 = -INFINITY;
        #pragma unroll
        for (int nt = 0; nt < 8; nt++) {
            rm0 = fmaxf(rm0, fmaxf(S[nt][0], S[nt][1]));
            rm1 = fmaxf(rm1, fmaxf(S[nt][2], S[nt][3]));
        }
        #pragma unroll
        for (int o = 1; o <= 2; o <<= 1) {
            rm0 = fmaxf(rm0, __shfl_xor_sync(0xffffffffu, rm0, o));
            rm1 = fmaxf(rm1, __shfl_xor_sync(0xffffffffu, rm1, o));
        }
        float mn0 = fmaxf(m0, rm0), mn1 = fmaxf(m1, rm1);
        float cor0 = __expf(m0 - mn0), cor1 = __expf(m1 - mn1);
        m0 = mn0; m1 = mn1;
        float rs0 = 0.f, rs1 = 0.f;
        #pragma unroll
        for (int nt = 0; nt < 8; nt++) {
            float p0 = __expf(S[nt][0] - mn0);
            float p1 = __expf(S[nt][1] - mn0);
            float p2 = __expf(S[nt][2] - mn1);
            float p3 = __expf(S[nt][3] - mn1);
            rs0 += p0 + p1; rs1 += p2 + p3;
            // store P fragments to smem (own warp rows), tf32
            *(uint2*)&QPs[(qrow + g)     * SQT + nt * 8 + 2 * tg] =
                make_uint2(f2tf(p0), f2tf(p1));
            *(uint2*)&QPs[(qrow + g + 8) * SQT + nt * 8 + 2 * tg] =
                make_uint2(f2tf(p2), f2tf(p3));
        }
        #pragma unroll
        for (int o = 1; o <= 2; o <<= 1) {
            rs0 += __shfl_xor_sync(0xffffffffu, rs0, o);
            rs1 += __shfl_xor_sync(0xffffffffu, rs1, o);
        }
        l0 = l0 * cor0 + rs0;
        l1 = l1 * cor1 + rs1;
        #pragma unroll
        for (int nt = 0; nt < 8; nt++) {
            oacc[nt][0] *= cor0; oacc[nt][1] *= cor0;
            oacc[nt][2] *= cor1; oacc[nt][3] *= cor1;
        }
        __syncwarp();

        // ---- O += P V : k over 64 keys, n over 64 dims ----
        #pragma unroll
        for (int kt = 0; kt < 8; kt++) {
            uint32_t pa[4];
            pa[0] = QPs[(qrow + g)     * SQT + kt * 8 + tg];
            pa[1] = QPs[(qrow + g + 8) * SQT + kt * 8 + tg];
            pa[2] = QPs[(qrow + g)     * SQT + kt * 8 + tg + 4];
            pa[3] = QPs[(qrow + g + 8) * SQT + kt * 8 + tg + 4];
            #pragma unroll
            for (int nt = 0; nt < 8; nt++) {
                uint32_t bfr[2];
                bfr[0] = Vs[(kt * 8 + tg)     * SQT + nt * 8 + g];
                bfr[1] = Vs[(kt * 8 + tg + 4) * SQT + nt * 8 + g];
                mma_tf32(oacc[nt], pa, bfr);
            }
        }
        __syncthreads();
    }

    // ---- normalize, optional SiLU, store ----
    float inv0 = 1.0f / l0, inv1 = 1.0f / l1;
    float* d0 = Og + base + (size_t)aq0 * DIM + 2 * tg;
    float* d1 = Og + base + (size_t)aq1 * DIM + 2 * tg;
    #pragma unroll
    for (int nt = 0; nt < 8; nt++) {
        float v0 = oacc[nt][0] * inv0, v1 = oacc[nt][1] * inv0;
        float v2 = oacc[nt][2] * inv1, v3 = oacc[nt][3] * inv1;
        if (do_silu) {
            v0 = v0 / (1.0f + __expf(-v0));
            v1 = v1 / (1.0f + __expf(-v1));
            v2 = v2 / (1.0f + __expf(-v2));
            v3 = v3 / (1.0f + __expf(-v3));
        }
        *(float2*)(d0 + nt * 8) = make_float2(v0, v1);
        *(float2*)(d1 + nt * 8) = make_float2(v2, v3);
    }
}

// ---------------- launch ----------------------------------------------------
extern "C" void kernel_launch(void* const* d_in, const int* in_sizes, int n_in,
                              void* d_out, int out_size)
{
    const float* tokens = (const float*)d_in[0];
    const float* gamma  = (const float*)d_in[1];
    const float* Wq     = (const float*)d_in[2];
    const float* Wk     = (const float*)d_in[3];
    const float* Wv     = (const float*)d_in[4];
    const float* Wo     = (const float*)d_in[5];
    float* out = (float*)d_out;

    float *xn, *pa, *pb, *kb, *vb;
    cudaGetSymbolAddress((void**)&xn, g_xn);
    cudaGetSymbolAddress((void**)&pa, g_pa);
    cudaGetSymbolAddress((void**)&pb, g_pb);
    cudaGetSymbolAddress((void**)&kb, g_k);
    cudaGetSymbolAddress((void**)&vb, g_v);

    const size_t SZ = (size_t)MROWS * DIM;

    rope_tables_kernel<<<(NSEQ * 32 + 255) / 256, 256>>>();
    rmsnorm_kernel<<<MROWS, 256>>>(tokens, gamma, xn);

    size_t gsm = (size_t)(2 * ASZ + 2 * BSZ) * sizeof(uint32_t);  // 71,680 B
    cudaFuncSetAttribute(tgemm_kernel,
                         cudaFuncAttributeMaxDynamicSharedMemorySize, (int)gsm);
    cudaFuncSetAttribute(tgemm7_kernel,
                         cudaFuncAttributeMaxDynamicSharedMemorySize, (int)gsm);

    dim3 g7(DIM / 128, MROWS / 128, 7);
    tgemm7_kernel<<<g7, 256, gsm>>>(xn, Wq, Wk, Wv, pa, kb, vb);

    size_t asm_ = (size_t)3 * 64 * SQT * sizeof(uint32_t);        // 52,224 B
    cudaFuncSetAttribute(attn_mma_kernel,
                         cudaFuncAttributeMaxDynamicSharedMemorySize, (int)asm_);
    dim3 ga(NSEQ / 64, NHEAD, 4);
    attn_mma_kernel<<<ga, 128, asm_>>>(pa, kb,          vb,          pb, 1);
    attn_mma_kernel<<<ga, 128, asm_>>>(pb, kb + SZ,     vb + SZ,     pa, 1);
    attn_mma_kernel<<<ga, 128, asm_>>>(pa, kb + 2 * SZ, vb + 2 * SZ, pb, 0);

    dim3 gg(DIM / 128, MROWS / 128);
    tgemm_kernel<<<gg, 256, gsm>>>(pb, Wo, out);
}